// round 14
// baseline (speedup 1.0000x reference)
#include <cuda_runtime.h>

typedef unsigned long long u64;
typedef unsigned int u32;

#define NCTA_DIR 64
#define CHUNK_F  11520          // floats per smem chunk buffer: sA 64*36 + sW 256*36
#define NBUF     3
#define SMEM_BYTES (NBUF * CHUNK_F * 4)

// ---------------------------------------------------------------------------
// Device scratch (static __device__ arrays — no allocation)
// ---------------------------------------------------------------------------
__device__ float g_h0[2][2][256 * 512];   // [dir][buf][B*H] layer-0 hidden (double buffered)
__device__ float g_h1[2][2][256 * 512];   // layer-1 hidden
__device__ float g_v1[2][256 * 256];      // layer-1 input (= FC0 output)
__device__ u32   g_cnt[2];                // barrier arrival counters
__device__ u32   g_gen[2];                // barrier generation (monotonic across replays)

// ---------------------------------------------------------------------------
// f32x2 packed-FMA helpers
// ---------------------------------------------------------------------------
__device__ __forceinline__ u64 pk2(float x, float y) {
    u64 r; asm("mov.b64 %0, {%1, %2};" : "=l"(r) : "f"(x), "f"(y)); return r;
}
__device__ __forceinline__ float sumhalves(u64 v) {
    float x, y; asm("mov.b64 {%0, %1}, %2;" : "=f"(x), "=f"(y) : "l"(v));
    return x + y;
}
__device__ __forceinline__ void fma2(u64& d, u64 a, u64 b) {
    asm("fma.rn.f32x2 %0, %1, %2, %0;" : "+l"(d) : "l"(a), "l"(b));
}

__device__ __forceinline__ float tanhap(float x) {
    float y; asm("tanh.approx.f32 %0, %1;" : "=f"(y) : "f"(x)); return y;
}
__device__ __forceinline__ float sigmf(float x) {
    return fmaf(0.5f, tanhap(0.5f * x), 0.5f);
}

// ---------------------------------------------------------------------------
// cp.async helpers (LDGSTS: gmem -> smem, no staging registers)
// ---------------------------------------------------------------------------
__device__ __forceinline__ void cp16(void* dst, const void* src) {
    u32 d = (u32)__cvta_generic_to_shared(dst);
    asm volatile("cp.async.cg.shared.global [%0], [%1], 16;" :: "r"(d), "l"(src));
}
__device__ __forceinline__ void cp_commit() {
    asm volatile("cp.async.commit_group;");
}
__device__ __forceinline__ void cp_wait1() {
    asm volatile("cp.async.wait_group 1;");
}
__device__ __forceinline__ void cp_wait0() {
    asm volatile("cp.async.wait_group 0;");
}

// ---------------------------------------------------------------------------
// Per-direction grid barrier over 64 co-resident CTAs.
// ---------------------------------------------------------------------------
__device__ __forceinline__ void dbar(int dir) {
    __syncthreads();
    if (threadIdx.x == 0) {
        __threadfence();                     // release (cumulative over CTA via bar)
        volatile u32* gv = &g_gen[dir];
        u32 old = *gv;                       // read BEFORE arriving
        if (atomicAdd(&g_cnt[dir], 1u) == NCTA_DIR - 1) {
            atomicExch(&g_cnt[dir], 0u);
            __threadfence();
            atomicAdd(&g_gen[dir], 1u);
        } else {
            while (*gv == old) { __nanosleep(32); }
        }
        __threadfence();                     // acquire
    }
    __syncthreads();
}

// ---------------------------------------------------------------------------
// smem chunk (per 32 k-values), rows stride 36 floats (144 B):
//   16B-aligned; inter-lane stride 144 B -> 9 quads (odd) -> conflict-free.
//   sA[64 rows][k] (2304 f) ; sW[256 rows][k] at +2304, row = gate*64 + unit.
// Triple buffered: base + (c%3)*CHUNK_F, depth-2 cp.async pipeline.
// ---------------------------------------------------------------------------

// Fused gate-GEMM + LSTM cell tile: 64 batch x (64 units x 4 gates), K = nchunks*32.
// 512 threads, 16 warps: warp w -> rowgroup rg=w>>1 (8 rows), unit-half hf=w&1.
// lane l -> unit hf*32+l, all 4 gates.  32 u64 accs; c state in registers.
__device__ __forceinline__ void gate_tile(
    const float* __restrict__ vin, int vstride,
    const float* __restrict__ hprev,
    const float* __restrict__ wih,   // [2048,256]
    const float* __restrict__ whh,   // [2048,512]
    const float* gb,                 // 4 per-thread gate biases
    float* __restrict__ hout,
    float* cst,                      // 8 cell states
    int btile, int utile, int nchunks,
    float* smbase)
{
    const int tid = threadIdx.x, lane = tid & 31, wrp = tid >> 5;
    const int hf = wrp & 1, rg = wrp >> 1;

    u64 acc[8][4];
#pragma unroll
    for (int r = 0; r < 8; ++r)
#pragma unroll
        for (int g = 0; g < 4; ++g) acc[r][g] = pk2(gb[g], 0.0f);

    const int r8A = tid >> 3, kqA = tid & 7;

    auto issue = [&](int c) {
        float* buf = smbase + (c % NBUF) * CHUNK_F;
        int kc = c * 32;
        // A: 64 rows x 32 k, 1 copy per thread
        {
            const float* src = (c < 8)
                ? vin   + (btile * 64 + r8A) * vstride + kc + kqA * 4
                : hprev + (btile * 64 + r8A) * 512 + (kc - 256) + kqA * 4;
            cp16(buf + r8A * 36 + kqA * 4, src);
        }
        // W: 256 rows x 32 k, 4 copies per thread
        float* sW = buf + 2304;
#pragma unroll
        for (int q = 0; q < 4; ++q) {
            int idx = tid + q * 512, j = idx >> 3, kq = idx & 7;
            // sW row j = gate*64 + ul -> weight row n = gate*512 + utile*64 + ul
            int n = (j >> 6) * 512 + utile * 64 + (j & 63);
            const float* src = (c < 8) ? (wih + n * 256 + kc + kq * 4)
                                       : (whh + n * 512 + (kc - 256) + kq * 4);
            cp16(sW + j * 36 + kq * 4, src);
        }
        cp_commit();
    };

    issue(0);
    if (nchunks > 1) issue(1);

#pragma unroll 1
    for (int c = 0; c < nchunks; ++c) {
        if (c + 1 < nchunks) cp_wait1(); else cp_wait0();
        __syncthreads();                     // chunk c visible to all warps;
                                             // also: everyone done reading buf (c+2)%3
        if (c + 2 < nchunks) issue(c + 2);   // overlaps with compute below

        float* sA = smbase + (c % NBUF) * CHUNK_F;
        float* sW = sA + 2304;
        const int ul = hf * 32 + lane;
#pragma unroll
        for (int kq4 = 0; kq4 < 8; ++kq4) {
            const int k = kq4 * 4;
            ulonglong2 w0 = *(const ulonglong2*)(sW + (ul      ) * 36 + k);
            ulonglong2 w1 = *(const ulonglong2*)(sW + (ul +  64) * 36 + k);
            ulonglong2 w2 = *(const ulonglong2*)(sW + (ul + 128) * 36 + k);
            ulonglong2 w3 = *(const ulonglong2*)(sW + (ul + 192) * 36 + k);
#pragma unroll
            for (int r = 0; r < 8; ++r) {
                ulonglong2 a = *(const ulonglong2*)(sA + (rg * 8 + r) * 36 + k);
                fma2(acc[r][0], a.x, w0.x); fma2(acc[r][0], a.y, w0.y);
                fma2(acc[r][1], a.x, w1.x); fma2(acc[r][1], a.y, w1.y);
                fma2(acc[r][2], a.x, w2.x); fma2(acc[r][2], a.y, w2.y);
                fma2(acc[r][3], a.x, w3.x); fma2(acc[r][3], a.y, w3.y);
            }
        }
    }

    // LSTM cell update (gate order i, f, g, o); c stays in registers
    const int u  = utile * 64 + hf * 32 + lane;
    const int rb = btile * 64 + rg * 8;
#pragma unroll
    for (int rr = 0; rr < 8; ++rr) {
        float gi = sumhalves(acc[rr][0]);
        float gf = sumhalves(acc[rr][1]);
        float gg = sumhalves(acc[rr][2]);
        float go = sumhalves(acc[rr][3]);
        float cc = sigmf(gf) * cst[rr] + sigmf(gi) * tanhap(gg);
        cst[rr] = cc;
        hout[(rb + rr) * 512 + u] = sigmf(go) * tanhap(cc);
    }
}

// ---------------------------------------------------------------------------
// FC tile: 64 batch x 32 cols, K = 512.  out = hin @ wfc^T + bfc
// 512 threads: warp w -> rows w*4..w*4+3 ; lane -> column.
// ---------------------------------------------------------------------------
__device__ __forceinline__ void fc_tile(
    const float* __restrict__ hin,   // [256,512]
    const float* __restrict__ wfc,   // [256,512]
    const float* __restrict__ bfc,
    float* __restrict__ outp, int ostride,
    int fb, int fv,
    float* smbase)
{
    const int tid = threadIdx.x, lane = tid & 31, wrp = tid >> 5;
    const int c0 = fv * 32 + lane;

    u64 acc[4];
    {
        u64 bb = pk2(bfc[c0], 0.0f);
#pragma unroll
        for (int r = 0; r < 4; ++r) acc[r] = bb;
    }

    const int r8A = tid >> 3, kqA = tid & 7;

    auto issue = [&](int c) {
        float* buf = smbase + (c % NBUF) * CHUNK_F;
        int kc = c * 32;
        cp16(buf + r8A * 36 + kqA * 4,
             hin + (fb * 64 + r8A) * 512 + kc + kqA * 4);
        if (tid < 256)
            cp16(buf + 2304 + r8A * 36 + kqA * 4,
                 wfc + (fv * 32 + r8A) * 512 + kc + kqA * 4);
        cp_commit();
    };

    issue(0); issue(1);

#pragma unroll 1
    for (int c = 0; c < 16; ++c) {
        if (c + 1 < 16) cp_wait1(); else cp_wait0();
        __syncthreads();
        if (c + 2 < 16) issue(c + 2);

        float* sA  = smbase + (c % NBUF) * CHUNK_F;
        float* sWf = sA + 2304;
#pragma unroll
        for (int kq4 = 0; kq4 < 8; ++kq4) {
            const int k = kq4 * 4;
            ulonglong2 w = *(const ulonglong2*)(sWf + lane * 36 + k);
#pragma unroll
            for (int r = 0; r < 4; ++r) {
                ulonglong2 a = *(const ulonglong2*)(sA + (wrp * 4 + r) * 36 + k);
                fma2(acc[r], a.x, w.x);
                fma2(acc[r], a.y, w.y);
            }
        }
    }

#pragma unroll
    for (int r = 0; r < 4; ++r) {
        int rr = fb * 64 + wrp * 4 + r;
        outp[rr * ostride + c0] = sumhalves(acc[r]);
    }
}

// ---------------------------------------------------------------------------
// Persistent kernel: 128 CTAs x 512 thr (64/direction), 2 barriers/step.
// Phase A(t): L0-gates(t) [CTAs 0-31] || L1-gates(t-1) [CTAs 32-63]
// Phase B(t): FC0(t)                 || FC1(t-1) -> d_out
// ---------------------------------------------------------------------------
__global__ void __launch_bounds__(512, 1)
bilstm_kernel(const float* __restrict__ x,
              const float* __restrict__ wih_l, const float* __restrict__ whh_l,
              const float* __restrict__ bih_l, const float* __restrict__ bhh_l,
              const float* __restrict__ wfc_l, const float* __restrict__ bfc_l,
              const float* __restrict__ wih_r, const float* __restrict__ whh_r,
              const float* __restrict__ bih_r, const float* __restrict__ bhh_r,
              const float* __restrict__ wfc_r, const float* __restrict__ bfc_r,
              float* __restrict__ out)
{
    extern __shared__ __align__(16) float smem[];   // NBUF * CHUNK_F floats

    const int dir  = (int)(blockIdx.x >> 6);
    const int r    = (int)(blockIdx.x & 63);
    const int lane = threadIdx.x & 31;
    const int wrp  = threadIdx.x >> 5;
    const int hf   = wrp & 1;

    const float* wih = dir ? wih_r : wih_l;
    const float* whh = dir ? whh_r : whh_l;
    const float* bih = dir ? bih_r : bih_l;
    const float* bhh = dir ? bhh_r : bhh_l;
    const float* wfc = dir ? wfc_r : wfc_l;
    const float* bfc = dir ? bfc_r : bfc_l;

    const bool isL0  = (r < 32);
    const int  gr    = isL0 ? r : (r - 32);
    const int  layer = isL0 ? 0 : 1;

    const int btile = gr >> 3;   // 4 batch tiles of 64
    const int utile = gr & 7;    // 8 unit tiles of 64
    const int fb = gr >> 3, fv = gr & 7;

    const float* gwih = wih + layer * 2048 * 256;
    const float* gwhh = whh + layer * 2048 * 512;
    const float* lbih = bih + layer * 2048;
    const float* lbhh = bhh + layer * 2048;
    const float* fwfc = wfc + layer * 256 * 512;
    const float* fbfc = bfc + layer * 256;

    float gb[4];
    {
        int u = utile * 64 + hf * 32 + lane;
#pragma unroll
        for (int g = 0; g < 4; ++g)
            gb[g] = lbih[g * 512 + u] + lbhh[g * 512 + u];
    }

    float cst[8];
#pragma unroll
    for (int i = 0; i < 8; ++i) cst[i] = 0.0f;

#pragma unroll 1
    for (int t = 0; t <= 255; ++t) {
        // ---------------- Phase A: gate GEMM + cell ----------------
        bool doG; const float* vin; int vs, nch; const float* hp; float* ho;
        if (isL0) {
            doG = (t < 255);
            int xc = dir ? (255 - t) : t;
            vin = x + xc * 256;  vs = 65536;
            nch = (t == 0) ? 8 : 24;
            hp = g_h0[dir][(t + 1) & 1];
            ho = g_h0[dir][t & 1];
        } else {
            int s = t - 1;
            doG = (s >= 0);
            vin = g_v1[dir];  vs = 256;
            nch = (s <= 0) ? 8 : 24;
            hp = g_h1[dir][(s + 1) & 1];
            ho = g_h1[dir][s & 1];
        }
        if (doG) {
            gate_tile(vin, vs, hp, gwih, gwhh, gb,
                      ho, cst, btile, utile, nch, smem);
        }
        dbar(dir);

        // ---------------- Phase B: FC layers ----------------
        bool doF; const float* hin; float* op; int os;
        if (isL0) {
            doF = (t < 255);
            hin = g_h0[dir][t & 1];
            op  = g_v1[dir];  os = 256;
        } else {
            int s = t - 1;
            doF = (s >= 0);
            hin = g_h1[dir][s & 1];
            int tcol = dir ? (255 + s) : s;
            op  = out + tcol * 256;  os = 510 * 256;
        }
        if (doF) fc_tile(hin, fwfc, fbfc, op, os, fb, fv, smem);
        dbar(dir);
    }
}

extern "C" void kernel_launch(void* const* d_in, const int* in_sizes, int n_in,
                              void* d_out, int out_size)
{
    (void)in_sizes; (void)n_in; (void)out_size;
    cudaFuncSetAttribute(bilstm_kernel,
                         cudaFuncAttributeMaxDynamicSharedMemorySize, SMEM_BYTES);
    bilstm_kernel<<<128, 512, SMEM_BYTES>>>(
        (const float*)d_in[0],
        (const float*)d_in[1],  (const float*)d_in[2],  (const float*)d_in[3],
        (const float*)d_in[4],  (const float*)d_in[5],  (const float*)d_in[6],
        (const float*)d_in[7],  (const float*)d_in[8],  (const float*)d_in[9],
        (const float*)d_in[10], (const float*)d_in[11], (const float*)d_in[12],
        (float*)d_out);
}

// round 15
// speedup vs baseline: 1.3634x; 1.3634x over previous
#include <cuda_runtime.h>

typedef unsigned long long u64;
typedef unsigned int u32;

#define NCTA_DIR 128
#define CHUNK_F  6912           // floats per smem chunk: sA 64*36 + sW 128*36
#define NBUF     3
#define SMEM_BYTES (NBUF * CHUNK_F * 4)

// ---------------------------------------------------------------------------
// Device scratch (static __device__ arrays — no allocation)
// ---------------------------------------------------------------------------
__device__ float g_h0[2][2][256 * 512];   // [dir][buf][B*H] layer-0 hidden (double buffered)
__device__ float g_h1[2][2][256 * 512];   // layer-1 hidden
__device__ float g_v1[2][256 * 256];      // layer-1 input (= FC0 output)
__device__ u32   g_cnt[2];                // barrier arrival counters
__device__ u32   g_gen[2];                // barrier generation (monotonic across replays)

// ---------------------------------------------------------------------------
// f32x2 packed-FMA helpers
// ---------------------------------------------------------------------------
__device__ __forceinline__ u64 pk2(float x, float y) {
    u64 r; asm("mov.b64 %0, {%1, %2};" : "=l"(r) : "f"(x), "f"(y)); return r;
}
__device__ __forceinline__ float sumhalves(u64 v) {
    float x, y; asm("mov.b64 {%0, %1}, %2;" : "=f"(x), "=f"(y) : "l"(v));
    return x + y;
}
__device__ __forceinline__ void fma2(u64& d, u64 a, u64 b) {
    asm("fma.rn.f32x2 %0, %1, %2, %0;" : "+l"(d) : "l"(a), "l"(b));
}

__device__ __forceinline__ float tanhap(float x) {
    float y; asm("tanh.approx.f32 %0, %1;" : "=f"(y) : "f"(x)); return y;
}
__device__ __forceinline__ float sigmf(float x) {
    return fmaf(0.5f, tanhap(0.5f * x), 0.5f);
}

// ---------------------------------------------------------------------------
// cp.async helpers (gmem -> smem, no staging registers)
// ---------------------------------------------------------------------------
__device__ __forceinline__ void cp16(void* dst, const void* src) {
    u32 d = (u32)__cvta_generic_to_shared(dst);
    asm volatile("cp.async.cg.shared.global [%0], [%1], 16;" :: "r"(d), "l"(src));
}
__device__ __forceinline__ void cp_commit() { asm volatile("cp.async.commit_group;"); }
__device__ __forceinline__ void cp_wait1()  { asm volatile("cp.async.wait_group 1;"); }
__device__ __forceinline__ void cp_wait0()  { asm volatile("cp.async.wait_group 0;"); }

// ---------------------------------------------------------------------------
// Per-direction grid barrier over 128 co-resident CTAs.
// ---------------------------------------------------------------------------
__device__ __forceinline__ void dbar(int dir) {
    __syncthreads();
    if (threadIdx.x == 0) {
        __threadfence();                     // release (cumulative over CTA via bar)
        volatile u32* gv = &g_gen[dir];
        u32 old = *gv;                       // read BEFORE arriving
        if (atomicAdd(&g_cnt[dir], 1u) == NCTA_DIR - 1) {
            atomicExch(&g_cnt[dir], 0u);
            __threadfence();
            atomicAdd(&g_gen[dir], 1u);
        } else {
            while (*gv == old) { __nanosleep(32); }
        }
        __threadfence();                     // acquire
    }
    __syncthreads();
}

// ---------------------------------------------------------------------------
// smem chunk (per 32 k-values), rows stride 36 floats (144 B):
//   16B-aligned; inter-lane stride 144 B -> 9 quads (odd) -> conflict-free.
//   sA[64 rows][k] (2304 f) ; sW[128 rows][k] at +2304, row = gate*32 + unit.
// Triple buffered: base + (c%3)*CHUNK_F, depth-2 cp.async pipeline.
// ---------------------------------------------------------------------------

// Fused gate-GEMM + LSTM cell tile: 64 batch x (32 units x 4 gates), K = nchunks*32.
// 256 threads, 8 warps: warp w -> batch rows w*8..w*8+7 ; lane -> unit, 4 gates.
__device__ __forceinline__ void gate_tile(
    const float* __restrict__ vin, int vstride,
    const float* __restrict__ hprev,
    const float* __restrict__ wih,   // [2048,256]
    const float* __restrict__ whh,   // [2048,512]
    const float* gb,                 // 4 per-thread gate biases
    float* __restrict__ hout,
    float* cst,                      // 8 cell states
    int btile, int utile, int nchunks,
    float* smbase)
{
    const int tid = threadIdx.x, lane = tid & 31, wrp = tid >> 5;

    u64 acc[8][4];
#pragma unroll
    for (int r = 0; r < 8; ++r)
#pragma unroll
        for (int g = 0; g < 4; ++g) acc[r][g] = pk2(gb[g], 0.0f);

    auto issue = [&](int c) {
        float* buf = smbase + (c % NBUF) * CHUNK_F;
        const int kc = c * 32, kh = kc - 256;
        // A: 64 rows x 32 k -> 2 cp16/thread
#pragma unroll
        for (int q = 0; q < 2; ++q) {
            int idx = tid + q * 256, r8 = idx >> 3, kq = idx & 7;
            const float* src = (c < 8)
                ? vin   + (btile * 64 + r8) * vstride + kc + kq * 4
                : hprev + (btile * 64 + r8) * 512     + kh + kq * 4;
            cp16(buf + r8 * 36 + kq * 4, src);
        }
        // W: 128 rows x 32 k -> 4 cp16/thread; sW row j = gate*32 + unit_local
        float* sW = buf + 2304;
#pragma unroll
        for (int q = 0; q < 4; ++q) {
            int idx = tid + q * 256, j = idx >> 3, kq = idx & 7;
            int n = (j >> 5) * 512 + utile * 32 + (j & 31);
            const float* src = (c < 8) ? (wih + n * 256 + kc + kq * 4)
                                       : (whh + n * 512 + kh + kq * 4);
            cp16(sW + j * 36 + kq * 4, src);
        }
        cp_commit();
    };

    issue(0);
    if (nchunks > 1) issue(1);

#pragma unroll 1
    for (int c = 0; c < nchunks; ++c) {
        if (c + 1 < nchunks) cp_wait1(); else cp_wait0();
        __syncthreads();                     // chunk c staged; buf (c+2)%3 free
        if (c + 2 < nchunks) issue(c + 2);   // overlaps with compute below

        float* sA = smbase + (c % NBUF) * CHUNK_F;
        float* sW = sA + 2304;
#pragma unroll
        for (int kq4 = 0; kq4 < 8; ++kq4) {
            const int k = kq4 * 4;
            ulonglong2 w0 = *(const ulonglong2*)(sW + (lane      ) * 36 + k);
            ulonglong2 w1 = *(const ulonglong2*)(sW + (lane + 32) * 36 + k);
            ulonglong2 w2 = *(const ulonglong2*)(sW + (lane + 64) * 36 + k);
            ulonglong2 w3 = *(const ulonglong2*)(sW + (lane + 96) * 36 + k);
#pragma unroll
            for (int r = 0; r < 8; ++r) {
                ulonglong2 a = *(const ulonglong2*)(sA + (wrp * 8 + r) * 36 + k);
                fma2(acc[r][0], a.x, w0.x); fma2(acc[r][0], a.y, w0.y);
                fma2(acc[r][1], a.x, w1.x); fma2(acc[r][1], a.y, w1.y);
                fma2(acc[r][2], a.x, w2.x); fma2(acc[r][2], a.y, w2.y);
                fma2(acc[r][3], a.x, w3.x); fma2(acc[r][3], a.y, w3.y);
            }
        }
    }

    // LSTM cell update (gate order i, f, g, o); c stays in registers
    const int u  = utile * 32 + lane;
    const int rb = btile * 64 + wrp * 8;
#pragma unroll
    for (int rr = 0; rr < 8; ++rr) {
        float gi = sumhalves(acc[rr][0]);
        float gf = sumhalves(acc[rr][1]);
        float gg = sumhalves(acc[rr][2]);
        float go = sumhalves(acc[rr][3]);
        float cc = sigmf(gf) * cst[rr] + sigmf(gi) * tanhap(gg);
        cst[rr] = cc;
        hout[(rb + rr) * 512 + u] = sigmf(go) * tanhap(cc);
    }
}

// ---------------------------------------------------------------------------
// FC tile: 32 batch x 32 cols, K = 512.  out = hin @ wfc^T + bfc
// 256 threads: warp w -> rows w*4..w*4+3 ; lane -> column.
// ---------------------------------------------------------------------------
__device__ __forceinline__ void fc_tile(
    const float* __restrict__ hin,   // [256,512]
    const float* __restrict__ wfc,   // [256,512]
    const float* __restrict__ bfc,
    float* __restrict__ outp, int ostride,
    int fb, int fv,
    float* smbase)
{
    const int tid = threadIdx.x, lane = tid & 31, wrp = tid >> 5;
    const int c0 = fv * 32 + lane;

    u64 acc[4];
    {
        u64 bb = pk2(bfc[c0], 0.0f);
#pragma unroll
        for (int r = 0; r < 4; ++r) acc[r] = bb;
    }

    const int r8 = tid >> 3, kq = tid & 7;
    auto issue = [&](int c) {
        float* buf = smbase + (c % NBUF) * CHUNK_F;
        int kc = c * 32;
        cp16(buf + r8 * 36 + kq * 4,
             hin + (fb * 32 + r8) * 512 + kc + kq * 4);
        cp16(buf + 2304 + r8 * 36 + kq * 4,
             wfc + (fv * 32 + r8) * 512 + kc + kq * 4);
        cp_commit();
    };

    issue(0); issue(1);

#pragma unroll 1
    for (int c = 0; c < 16; ++c) {
        if (c + 1 < 16) cp_wait1(); else cp_wait0();
        __syncthreads();
        if (c + 2 < 16) issue(c + 2);

        float* sA  = smbase + (c % NBUF) * CHUNK_F;
        float* sWf = sA + 2304;
#pragma unroll
        for (int kq4 = 0; kq4 < 8; ++kq4) {
            const int k = kq4 * 4;
            ulonglong2 w = *(const ulonglong2*)(sWf + lane * 36 + k);
#pragma unroll
            for (int r = 0; r < 4; ++r) {
                ulonglong2 a = *(const ulonglong2*)(sA + (wrp * 4 + r) * 36 + k);
                fma2(acc[r], a.x, w.x);
                fma2(acc[r], a.y, w.y);
            }
        }
    }

#pragma unroll
    for (int r = 0; r < 4; ++r) {
        int rr = fb * 32 + wrp * 4 + r;
        outp[rr * ostride + c0] = sumhalves(acc[r]);
    }
}

// ---------------------------------------------------------------------------
// Persistent kernel: 256 CTAs x 256 thr, 2 CTAs/SM (4 warps/SMSP).
// Per direction 128 CTAs, 2 barriers/step:
// Phase A(t): L0-gates(t) [CTAs 0-63] || L1-gates(t-1) [CTAs 64-127]
// Phase B(t): FC0(t)                  || FC1(t-1) -> d_out
// ---------------------------------------------------------------------------
__global__ void __launch_bounds__(256, 2)
bilstm_kernel(const float* __restrict__ x,
              const float* __restrict__ wih_l, const float* __restrict__ whh_l,
              const float* __restrict__ bih_l, const float* __restrict__ bhh_l,
              const float* __restrict__ wfc_l, const float* __restrict__ bfc_l,
              const float* __restrict__ wih_r, const float* __restrict__ whh_r,
              const float* __restrict__ bih_r, const float* __restrict__ bhh_r,
              const float* __restrict__ wfc_r, const float* __restrict__ bfc_r,
              float* __restrict__ out)
{
    extern __shared__ __align__(16) float smem[];   // NBUF * CHUNK_F floats

    const int dir  = (int)(blockIdx.x >> 7);
    const int r    = (int)(blockIdx.x & 127);
    const int lane = threadIdx.x & 31;

    const float* wih = dir ? wih_r : wih_l;
    const float* whh = dir ? whh_r : whh_l;
    const float* bih = dir ? bih_r : bih_l;
    const float* bhh = dir ? bhh_r : bhh_l;
    const float* wfc = dir ? wfc_r : wfc_l;
    const float* bfc = dir ? bfc_r : bfc_l;

    const bool isL0  = (r < 64);
    const int  gr    = isL0 ? r : (r - 64);
    const int  layer = isL0 ? 0 : 1;

    const int btile = gr >> 4;   // 4 batch tiles of 64
    const int utile = gr & 15;   // 16 unit tiles of 32
    const int fb = gr >> 3;      // 8 batch tiles of 32 (FC)
    const int fv = gr & 7;       // 8 col tiles of 32 (FC)

    const float* gwih = wih + layer * 2048 * 256;
    const float* gwhh = whh + layer * 2048 * 512;
    const float* lbih = bih + layer * 2048;
    const float* lbhh = bhh + layer * 2048;
    const float* fwfc = wfc + layer * 256 * 512;
    const float* fbfc = bfc + layer * 256;

    float gb[4];
    {
        int u = utile * 32 + lane;
#pragma unroll
        for (int g = 0; g < 4; ++g)
            gb[g] = lbih[g * 512 + u] + lbhh[g * 512 + u];
    }

    float cst[8];
#pragma unroll
    for (int i = 0; i < 8; ++i) cst[i] = 0.0f;

#pragma unroll 1
    for (int t = 0; t <= 255; ++t) {
        // ---------------- Phase A: gate GEMM + cell ----------------
        bool doG; const float* vin; int vs, nch; const float* hp; float* ho;
        if (isL0) {
            doG = (t < 255);
            int xc = dir ? (255 - t) : t;
            vin = x + xc * 256;  vs = 65536;
            nch = (t == 0) ? 8 : 24;
            hp = g_h0[dir][(t + 1) & 1];
            ho = g_h0[dir][t & 1];
        } else {
            int s = t - 1;
            doG = (s >= 0);
            vin = g_v1[dir];  vs = 256;
            nch = (s <= 0) ? 8 : 24;
            hp = g_h1[dir][(s + 1) & 1];
            ho = g_h1[dir][s & 1];
        }
        if (doG) {
            gate_tile(vin, vs, hp, gwih, gwhh, gb,
                      ho, cst, btile, utile, nch, smem);
        }
        dbar(dir);

        // ---------------- Phase B: FC layers ----------------
        bool doF; const float* hin; float* op; int os;
        if (isL0) {
            doF = (t < 255);
            hin = g_h0[dir][t & 1];
            op  = g_v1[dir];  os = 256;
        } else {
            int s = t - 1;
            doF = (s >= 0);
            hin = g_h1[dir][s & 1];
            int tcol = dir ? (255 + s) : s;
            op  = out + tcol * 256;  os = 510 * 256;
        }
        if (doF) fc_tile(hin, fwfc, fbfc, op, os, fb, fv, smem);
        dbar(dir);
    }
}

extern "C" void kernel_launch(void* const* d_in, const int* in_sizes, int n_in,
                              void* d_out, int out_size)
{
    (void)in_sizes; (void)n_in; (void)out_size;
    cudaFuncSetAttribute(bilstm_kernel,
                         cudaFuncAttributeMaxDynamicSharedMemorySize, SMEM_BYTES);
    bilstm_kernel<<<256, 256, SMEM_BYTES>>>(
        (const float*)d_in[0],
        (const float*)d_in[1],  (const float*)d_in[2],  (const float*)d_in[3],
        (const float*)d_in[4],  (const float*)d_in[5],  (const float*)d_in[6],
        (const float*)d_in[7],  (const float*)d_in[8],  (const float*)d_in[9],
        (const float*)d_in[10], (const float*)d_in[11], (const float*)d_in[12],
        (float*)d_out);
}